// round 1
// baseline (speedup 1.0000x reference)
#include <cuda_runtime.h>
#include <cuda_bf16.h>
#include <math.h>

// Problem constants
#define BB   4
#define LL   1024
#define HID  2048
#define HH   16
#define DK   128
#define DV   128
#define KSZ  4
#define KEY_DIM  (HH*DK)            // 2048
#define VAL_DIM  (HH*DV)            // 2048
#define CONV_DIM (2*KEY_DIM+VAL_DIM) // 6144
#define QKVZ_DIM (2*KEY_DIM+2*VAL_DIM) // 8192
#define BL   (BB*LL)                // 4096

// ---------------- scratch (static device allocations) ----------------
__device__ float g_qkvz[(size_t)BL * QKVZ_DIM];   // 134 MB
__device__ float g_ba  [(size_t)BL * 2 * HH];
__device__ float g_xqkv[(size_t)BL * CONV_DIM];   // 100 MB : q,k normalized + v
__device__ float g_g   [(size_t)BL * HH];
__device__ float g_beta[(size_t)BL * HH];
__device__ float g_o   [(size_t)BL * VAL_DIM];    // 33.5 MB core output, gated in place

// ---------------- fp32 SGEMM: C[M,N] = A[M,K] @ B[K,N], all row-major ----------------
// 128x128 block tile, BK=8, 256 threads, 8x8 per thread. Dims must be multiples of 128/8.
__global__ __launch_bounds__(256, 2)
void sgemm128(const float* __restrict__ A, const float* __restrict__ B,
              float* __restrict__ C, int M, int N, int K)
{
    __shared__ float As[8][128];
    __shared__ float Bs[8][128];
    const int bx = blockIdx.x;   // N tile
    const int by = blockIdx.y;   // M tile
    const int tid = threadIdx.x;
    const int tx = tid % 16;
    const int ty = tid / 16;

    const float* Ab = A + (size_t)by * 128 * K;
    const float* Bb = B + (size_t)bx * 128;

    const int aRow = tid >> 1;          // 0..127
    const int aCol = (tid & 1) * 4;     // 0 or 4
    const int bRow = tid >> 5;          // 0..7
    const int bCol = (tid & 31) * 4;

    float acc[8][8];
    #pragma unroll
    for (int i = 0; i < 8; i++)
        #pragma unroll
        for (int j = 0; j < 8; j++) acc[i][j] = 0.f;

    float ra[8], rb[8];

    for (int k0 = 0; k0 < K; k0 += 8) {
        float4 av = *(const float4*)(Ab + (size_t)aRow * K + k0 + aCol);
        float4 bv = *(const float4*)(Bb + (size_t)(k0 + bRow) * N + bCol);
        As[aCol+0][aRow] = av.x;
        As[aCol+1][aRow] = av.y;
        As[aCol+2][aRow] = av.z;
        As[aCol+3][aRow] = av.w;
        *(float4*)&Bs[bRow][bCol] = bv;
        __syncthreads();
        #pragma unroll
        for (int kk = 0; kk < 8; kk++) {
            #pragma unroll
            for (int i = 0; i < 8; i++) ra[i] = As[kk][ty*8+i];
            #pragma unroll
            for (int j = 0; j < 8; j++) rb[j] = Bs[kk][tx*8+j];
            #pragma unroll
            for (int i = 0; i < 8; i++)
                #pragma unroll
                for (int j = 0; j < 8; j++)
                    acc[i][j] = fmaf(ra[i], rb[j], acc[i][j]);
        }
        __syncthreads();
    }

    float* Cb = C + (size_t)(by*128 + ty*8) * N + bx*128 + tx*8;
    #pragma unroll
    for (int i = 0; i < 8; i++) {
        *(float4*)(Cb + (size_t)i * N + 0) = make_float4(acc[i][0], acc[i][1], acc[i][2], acc[i][3]);
        *(float4*)(Cb + (size_t)i * N + 4) = make_float4(acc[i][4], acc[i][5], acc[i][6], acc[i][7]);
    }
}

// ---------------- small GEMM for ba: [BL,2048] @ [2048,32] ----------------
__global__ void ba_gemm_kernel(const float* __restrict__ hidden,
                               const float* __restrict__ W_ba)
{
    int m = blockIdx.x * blockDim.y + threadIdx.y;
    int n = threadIdx.x;               // 0..31
    const float* a = hidden + (size_t)m * HID;
    float acc = 0.f;
    #pragma unroll 8
    for (int k = 0; k < HID; k++)
        acc = fmaf(a[k], W_ba[k * 32 + n], acc);
    g_ba[(size_t)m * 32 + n] = acc;
}

// ---------------- causal depthwise conv (KS=4) + l2norm of q,k ----------------
// grid: (BL, 48), block: 128.  groups 0..15 = q heads, 16..31 = k heads, 32..47 = v heads
__global__ void conv_act_kernel(const float* __restrict__ conv_w,
                                const float* __restrict__ conv_b)
{
    int bl  = blockIdx.x;
    int grp = blockIdx.y;
    int c   = grp * 128 + threadIdx.x;
    int l   = bl & (LL - 1);

    const float* base = g_qkvz + (size_t)bl * QKVZ_DIM + c;
    float w0 = conv_w[c*KSZ+0], w1 = conv_w[c*KSZ+1],
          w2 = conv_w[c*KSZ+2], w3 = conv_w[c*KSZ+3];
    float acc = conv_b[c];
    if (l >= 3) acc = fmaf(base[-3*QKVZ_DIM], w0, acc);
    if (l >= 2) acc = fmaf(base[-2*QKVZ_DIM], w1, acc);
    if (l >= 1) acc = fmaf(base[-1*QKVZ_DIM], w2, acc);
    acc = fmaf(base[0], w3, acc);

    if (grp < 32) {      // q or k head: l2 normalize over the 128 channels of this block
        float ss = acc * acc;
        #pragma unroll
        for (int off = 16; off > 0; off >>= 1)
            ss += __shfl_xor_sync(0xffffffffu, ss, off);
        __shared__ float ws[4];
        if ((threadIdx.x & 31) == 0) ws[threadIdx.x >> 5] = ss;
        __syncthreads();
        float tot = ws[0] + ws[1] + ws[2] + ws[3];
        acc *= rsqrtf(tot + 1e-6f);
    }
    g_xqkv[(size_t)bl * CONV_DIM + c] = acc;
}

// ---------------- g / beta ----------------
__global__ void gate_kernel(const float* __restrict__ A_log,
                            const float* __restrict__ dt_bias)
{
    int i = blockIdx.x * blockDim.x + threadIdx.x;   // < BL*HH
    if (i >= BL * HH) return;
    int h = i & (HH - 1);
    int bl = i >> 4;
    float b_ = g_ba[(size_t)bl * 32 + h];
    float a_ = g_ba[(size_t)bl * 32 + 16 + h];
    float x  = a_ + dt_bias[h];
    float sp = (x > 20.f) ? x : log1pf(expf(x));
    g_g[i]    = -expf(A_log[h]) * sp;
    g_beta[i] = 1.f / (1.f + expf(-b_));
}

// ---------------- sequential delta-rule scan ----------------
// grid: (B*H, 2 dv-halves) = 128 blocks; block 128 threads.
// thread owns rows [rh*64, rh*64+64) of state column (half*64 + col), in registers.
__global__ __launch_bounds__(128)
void scan_kernel()
{
    const int bh   = blockIdx.x;      // 0..63
    const int half = blockIdx.y;      // 0/1
    const int b = bh >> 4, h = bh & 15;
    const int tid = threadIdx.x;
    const int col = tid & 63;
    const int rh  = tid >> 6;

    __shared__ float sk[128], sq[128], sv[64], red[128], red2[128];

    float S[64];
    #pragma unroll
    for (int r = 0; r < 64; r++) S[r] = 0.f;

    const float scale = 0.08838834764831845f;  // 128^-0.5

    const size_t xbase = (size_t)b * LL * CONV_DIM + (size_t)h * 128;
    const size_t gbase = (size_t)b * LL * HH + h;

    // prefetch l = 0
    const float* xp = g_xqkv + xbase;
    float qn = xp[tid];
    float kn = xp[2*KEY_DIM/2 + tid];              // +2048 (k block)
    float vn = (tid < 64) ? xp[2*KEY_DIM + half*64 + tid] : 0.f;  // +4096
    float gn = g_g[gbase];
    float bn = g_beta[gbase];

    for (int l = 0; l < LL; l++) {
        sq[tid] = qn; sk[tid] = kn;
        if (tid < 64) sv[tid] = vn;
        float gcur = gn, bcur = bn;
        __syncthreads();                                // (1) tiles visible

        if (l + 1 < LL) {                               // prefetch next step
            const float* xn = g_xqkv + xbase + (size_t)(l + 1) * CONV_DIM;
            qn = xn[tid];
            kn = xn[2048 + tid];
            if (tid < 64) vn = xn[4096 + half*64 + tid];
            gn = g_g[gbase + (size_t)(l + 1) * HH];
            bn = g_beta[gbase + (size_t)(l + 1) * HH];
        }

        float decay = expf(gcur);
        const float* skh = sk + rh * 64;
        float p0 = 0.f, p1 = 0.f, p2 = 0.f, p3 = 0.f;
        #pragma unroll
        for (int r = 0; r < 64; r += 4) {
            S[r+0] *= decay; p0 = fmaf(skh[r+0], S[r+0], p0);
            S[r+1] *= decay; p1 = fmaf(skh[r+1], S[r+1], p1);
            S[r+2] *= decay; p2 = fmaf(skh[r+2], S[r+2], p2);
            S[r+3] *= decay; p3 = fmaf(skh[r+3], S[r+3], p3);
        }
        red[tid] = (p0 + p1) + (p2 + p3);
        __syncthreads();                                // (2) partials visible

        float delta = (sv[col] - (red[col] + red[col + 64])) * bcur;

        const float* sqh = sq + rh * 64;
        p0 = p1 = p2 = p3 = 0.f;
        #pragma unroll
        for (int r = 0; r < 64; r += 4) {
            S[r+0] = fmaf(skh[r+0], delta, S[r+0]); p0 = fmaf(sqh[r+0], S[r+0], p0);
            S[r+1] = fmaf(skh[r+1], delta, S[r+1]); p1 = fmaf(sqh[r+1], S[r+1], p1);
            S[r+2] = fmaf(skh[r+2], delta, S[r+2]); p2 = fmaf(sqh[r+2], S[r+2], p2);
            S[r+3] = fmaf(skh[r+3], delta, S[r+3]); p3 = fmaf(sqh[r+3], S[r+3], p3);
        }
        red2[tid] = (p0 + p1) + (p2 + p3);
        __syncthreads();                                // (3) o partials visible

        if (rh == 0) {
            size_t oi = ((size_t)(b * LL + l)) * VAL_DIM + h * 128 + half * 64 + col;
            g_o[oi] = (red2[col] + red2[col + 64]) * scale;
        }
    }
}

// ---------------- RMS-style norm over DV + z gating (in place on g_o) ----------------
// grid: BL*HH blocks, block 128 (=DV)
__global__ void norm_gate_kernel(const float* __restrict__ norm_w)
{
    int blh = blockIdx.x;             // (b*L+l)*16 + h
    int d   = threadIdx.x;
    size_t oi = (size_t)blh * DV + d;
    float o = g_o[oi];
    float ss = o * o;
    #pragma unroll
    for (int off = 16; off > 0; off >>= 1)
        ss += __shfl_xor_sync(0xffffffffu, ss, off);
    __shared__ float ws[4];
    if ((d & 31) == 0) ws[d >> 5] = ss;
    __syncthreads();
    float tot = ws[0] + ws[1] + ws[2] + ws[3];

    int bl = blh >> 4, h = blh & 15;
    float z = g_qkvz[(size_t)bl * QKVZ_DIM + CONV_DIM + h * DV + d];
    float sig = 1.f / (1.f + expf(-z));
    g_o[oi] = o * rsqrtf(tot * (1.f / DV) + 1e-6f) * norm_w[d] * sig;
}

// ---------------- launch ----------------
extern "C" void kernel_launch(void* const* d_in, const int* in_sizes, int n_in,
                              void* d_out, int out_size)
{
    const float* hidden  = (const float*)d_in[0];
    const float* W_qkvz  = (const float*)d_in[1];
    const float* W_ba    = (const float*)d_in[2];
    const float* conv_w  = (const float*)d_in[3];
    const float* conv_b  = (const float*)d_in[4];
    const float* A_log   = (const float*)d_in[5];
    const float* dt_bias = (const float*)d_in[6];
    const float* norm_w  = (const float*)d_in[7];
    const float* W_out   = (const float*)d_in[8];
    float* out = (float*)d_out;

    float *qkvz_p = nullptr, *o_p = nullptr;
    cudaGetSymbolAddress((void**)&qkvz_p, g_qkvz);
    cudaGetSymbolAddress((void**)&o_p,    g_o);

    // 1) big projection GEMM: [4096,2048] @ [2048,8192]
    sgemm128<<<dim3(QKVZ_DIM/128, BL/128), 256>>>(hidden, W_qkvz, qkvz_p, BL, QKVZ_DIM, HID);

    // 2) ba projection: [4096,2048] @ [2048,32]
    ba_gemm_kernel<<<BL/8, dim3(32, 8)>>>(hidden, W_ba);

    // 3) causal conv + q/k l2norm
    conv_act_kernel<<<dim3(BL, CONV_DIM/128), 128>>>(conv_w, conv_b);

    // 4) g / beta
    gate_kernel<<<(BL*HH + 255)/256, 256>>>(A_log, dt_bias);

    // 5) gated delta-rule scan
    scan_kernel<<<dim3(BB*HH, 2), 128>>>();

    // 6) norm + z gate
    norm_gate_kernel<<<BL*HH, 128>>>(norm_w);

    // 7) output GEMM: [4096,2048] @ [2048,2048]
    sgemm128<<<dim3(VAL_DIM/128, BL/128), 256>>>(o_p, W_out, out, BL, VAL_DIM, HID);
}

// round 7
// speedup vs baseline: 1.8773x; 1.8773x over previous
#include <cuda_runtime.h>
#include <cuda_bf16.h>
#include <math.h>

// Problem constants
#define BB   4
#define LL   1024
#define HID  2048
#define HH   16
#define DK   128
#define DV   128
#define KSZ  4
#define KEY_DIM  (HH*DK)             // 2048
#define VAL_DIM  (HH*DV)             // 2048
#define CONV_DIM (2*KEY_DIM+VAL_DIM) // 6144
#define QKVZ_DIM (2*KEY_DIM+2*VAL_DIM) // 8192
#define BL   (BB*LL)                 // 4096

// ---------------- scratch (static device allocations) ----------------
__device__ float g_qkvz[(size_t)BL * QKVZ_DIM];
__device__ float g_ba  [(size_t)BL * 2 * HH];
__device__ float g_xqkv[(size_t)BL * CONV_DIM];
__device__ float g_g   [(size_t)BL * HH];
__device__ float g_beta[(size_t)BL * HH];
__device__ float g_o   [(size_t)BL * VAL_DIM];

__device__ __nv_bfloat16 g_hid_h[(size_t)BL * HID];
__device__ __nv_bfloat16 g_hid_l[(size_t)BL * HID];
__device__ __nv_bfloat16 g_Wq_h [(size_t)QKVZ_DIM * HID];  // transposed [N][K]
__device__ __nv_bfloat16 g_Wq_l [(size_t)QKVZ_DIM * HID];
__device__ __nv_bfloat16 g_Wo_h [(size_t)VAL_DIM * HID];   // transposed [N][K]
__device__ __nv_bfloat16 g_Wo_l [(size_t)VAL_DIM * HID];
__device__ __nv_bfloat16 g_o_h  [(size_t)BL * VAL_DIM];
__device__ __nv_bfloat16 g_o_l  [(size_t)BL * VAL_DIM];

// ---------------- helpers ----------------
__device__ __forceinline__ void split2(float x, __nv_bfloat16& h, __nv_bfloat16& l) {
    h = __float2bfloat16_rn(x);
    l = __float2bfloat16_rn(x - __bfloat162float(h));
}
__device__ __forceinline__ unsigned s2u(const void* p) {
    return (unsigned)__cvta_generic_to_shared(p);
}
#define CP16(daddr, gptr) \
    asm volatile("cp.async.cg.shared.global [%0], [%1], 16;\n" :: "r"(daddr), "l"(gptr))
#define CP_COMMIT() asm volatile("cp.async.commit_group;\n")
#define CP_WAIT(n)  asm volatile("cp.async.wait_group %0;\n" :: "n"(n))
#define LDSM4(r, addr) \
    asm volatile("ldmatrix.sync.aligned.m8n8.x4.shared.b16 {%0,%1,%2,%3}, [%4];\n" \
                 : "=r"((r)[0]), "=r"((r)[1]), "=r"((r)[2]), "=r"((r)[3]) : "r"(addr))
#define MMA_BF16(d, a, b0, b1) \
    asm volatile("mma.sync.aligned.m16n8k16.row.col.f32.bf16.bf16.f32 " \
                 "{%0,%1,%2,%3}, {%4,%5,%6,%7}, {%8,%9}, {%0,%1,%2,%3};\n" \
                 : "+f"((d)[0]), "+f"((d)[1]), "+f"((d)[2]), "+f"((d)[3]) \
                 : "r"((a)[0]), "r"((a)[1]), "r"((a)[2]), "r"((a)[3]), \
                   "r"(b0), "r"(b1))

// ---------------- split (elementwise) ----------------
__global__ void split_kernel(const float* __restrict__ X,
                             __nv_bfloat16* __restrict__ H,
                             __nv_bfloat16* __restrict__ L, size_t n4)
{
    size_t i = (size_t)blockIdx.x * blockDim.x + threadIdx.x;
    if (i >= n4) return;
    float4 v = ((const float4*)X)[i];
    __nv_bfloat16 h0,h1,h2,h3,l0,l1,l2,l3;
    split2(v.x,h0,l0); split2(v.y,h1,l1); split2(v.z,h2,l2); split2(v.w,h3,l3);
    __nv_bfloat162* Hp = (__nv_bfloat162*)(H + i*4);
    __nv_bfloat162* Lp = (__nv_bfloat162*)(L + i*4);
    Hp[0] = __nv_bfloat162(h0,h1); Hp[1] = __nv_bfloat162(h2,h3);
    Lp[0] = __nv_bfloat162(l0,l1); Lp[1] = __nv_bfloat162(l2,l3);
}

// ---------------- split + transpose: W[K][N] -> T[N][K] (hi/lo) ----------------
__global__ void split_transpose_kernel(const float* __restrict__ W,
                                       __nv_bfloat16* __restrict__ Th,
                                       __nv_bfloat16* __restrict__ Tl,
                                       int K, int N)
{
    __shared__ float t[32][33];
    int k0 = blockIdx.y * 32, n0 = blockIdx.x * 32;
    int tx = threadIdx.x, ty = threadIdx.y;
    #pragma unroll
    for (int i = 0; i < 4; i++)
        t[ty + i*8][tx] = W[(size_t)(k0 + ty + i*8) * N + n0 + tx];
    __syncthreads();
    #pragma unroll
    for (int i = 0; i < 4; i++) {
        int n = ty + i*8;
        float x = t[tx][n];
        __nv_bfloat16 h, l; split2(x, h, l);
        size_t o = (size_t)(n0 + n) * K + k0 + tx;
        Th[o] = h; Tl[o] = l;
    }
}

// ---------------- bf16x3 tensor-core GEMM (static 32KB smem, BK=16) ----------------
// C[M,N] = A[M,K] @ B[K,N]; A hi/lo [M][K]; B TRANSPOSED hi/lo [N][K].
// Block tile 128x128, 256 threads (warps 2x4, each 64x32), double-buffered BK=16.
// Smem tile: 128 rows x 32 bytes, XOR-swizzled: byte = row*32 + (kb ^ (((row>>2)&1)<<4)).
#define TILE_B   4096                 // bytes per tile (128*32)
#define STAGE_B  (4*TILE_B)           // Ah, Al, Bh, Bl

__global__ __launch_bounds__(256)
void gemm_bf16x3(const __nv_bfloat16* __restrict__ Ah, const __nv_bfloat16* __restrict__ Al,
                 const __nv_bfloat16* __restrict__ Bh, const __nv_bfloat16* __restrict__ Bl,
                 float* __restrict__ C, int M, int N, int K)
{
    __shared__ __align__(16) unsigned char smbuf[2 * STAGE_B];   // 32 KB static

    const int tid = threadIdx.x, lane = tid & 31, warp = tid >> 5;
    const int wr = warp >> 2, wc = warp & 3;
    const int bm = blockIdx.y * 128, bn = blockIdx.x * 128;

    const char* gA_h = (const char*)(Ah + (size_t)bm * K);
    const char* gA_l = (const char*)(Al + (size_t)bm * K);
    const char* gB_h = (const char*)(Bh + (size_t)bn * K);
    const char* gB_l = (const char*)(Bl + (size_t)bn * K);

    float acc[4][4][4];
    #pragma unroll
    for (int i = 0; i < 4; i++)
        #pragma unroll
        for (int j = 0; j < 4; j++)
            #pragma unroll
            for (int r = 0; r < 4; r++) acc[i][j][r] = 0.f;

    // producer coords: 256 threads x 1 chunk(16B) per tile per stage
    const int prow   = tid >> 1;                 // 0..127
    const int pkb    = (tid & 1) * 16;           // 0 / 16 byte offset in row
    const int pdst   = prow * 32 + (pkb ^ (((prow >> 2) & 1) << 4));
    const size_t pgo = (size_t)prow * K * 2 + pkb;   // global byte offset (before k0)

    // consumer ldmatrix coords
    const int lrow = (lane & 7) + ((lane >> 3) & 1) * 8;   // 0..15
    const int lkb  = (lane >> 4) * 16;                     // 0 / 16 bytes

    const int niter = K / 16;

    // ---- stage 0 load ----
    {
        unsigned char* base = smbuf;
        CP16(s2u(base + 0*TILE_B + pdst), gA_h + pgo);
        CP16(s2u(base + 1*TILE_B + pdst), gA_l + pgo);
        CP16(s2u(base + 2*TILE_B + pdst), gB_h + pgo);
        CP16(s2u(base + 3*TILE_B + pdst), gB_l + pgo);
    }
    CP_COMMIT();

    for (int it = 0; it < niter; it++) {
        const int s = it & 1;
        if (it + 1 < niter) {
            unsigned char* nb = smbuf + (s ^ 1) * STAGE_B;
            size_t go = pgo + (size_t)(it + 1) * 32;     // +16 cols * 2B
            CP16(s2u(nb + 0*TILE_B + pdst), gA_h + go);
            CP16(s2u(nb + 1*TILE_B + pdst), gA_l + go);
            CP16(s2u(nb + 2*TILE_B + pdst), gB_h + go);
            CP16(s2u(nb + 3*TILE_B + pdst), gB_l + go);
            CP_COMMIT();
            CP_WAIT(1);
        } else {
            CP_WAIT(0);
        }
        __syncthreads();

        unsigned char* base = smbuf + s * STAGE_B;
        unsigned char* sAh = base + 0*TILE_B;
        unsigned char* sAl = base + 1*TILE_B;
        unsigned char* sBh = base + 2*TILE_B;
        unsigned char* sBl = base + 3*TILE_B;

        unsigned afh[4][4], afl[4][4], bfh[2][4], bfl[2][4];
        #pragma unroll
        for (int mt = 0; mt < 4; mt++) {
            int r = wr*64 + mt*16 + lrow;
            int off = r * 32 + (lkb ^ (((r >> 2) & 1) << 4));
            LDSM4(afh[mt], s2u(sAh + off));
            LDSM4(afl[mt], s2u(sAl + off));
        }
        #pragma unroll
        for (int p = 0; p < 2; p++) {
            int r = wc*32 + p*16 + lrow;
            int off = r * 32 + (lkb ^ (((r >> 2) & 1) << 4));
            LDSM4(bfh[p], s2u(sBh + off));
            LDSM4(bfl[p], s2u(sBl + off));
        }
        #pragma unroll
        for (int mt = 0; mt < 4; mt++)
            #pragma unroll
            for (int nt = 0; nt < 4; nt++) {
                int p = nt >> 1, q = nt & 1;
                MMA_BF16(acc[mt][nt], afh[mt], bfh[p][q], bfh[p][2+q]);
                MMA_BF16(acc[mt][nt], afh[mt], bfl[p][q], bfl[p][2+q]);
                MMA_BF16(acc[mt][nt], afl[mt], bfh[p][q], bfh[p][2+q]);
            }
        __syncthreads();
    }

    const int g = lane >> 2, t4 = lane & 3;
    #pragma unroll
    for (int mt = 0; mt < 4; mt++) {
        #pragma unroll
        for (int nt = 0; nt < 4; nt++) {
            int row = bm + wr*64 + mt*16 + g;
            int col = bn + wc*32 + nt*8 + 2*t4;
            float2* p0 = (float2*)&C[(size_t)row * N + col];
            float2* p1 = (float2*)&C[(size_t)(row + 8) * N + col];
            *p0 = make_float2(acc[mt][nt][0], acc[mt][nt][1]);
            *p1 = make_float2(acc[mt][nt][2], acc[mt][nt][3]);
        }
    }
}

// ---------------- small GEMM for ba: [BL,2048] @ [2048,32] ----------------
__global__ void ba_gemm_kernel(const float* __restrict__ hidden,
                               const float* __restrict__ W_ba)
{
    int m = blockIdx.x * blockDim.y + threadIdx.y;
    int n = threadIdx.x;
    const float* a = hidden + (size_t)m * HID;
    float acc = 0.f;
    #pragma unroll 8
    for (int k = 0; k < HID; k++)
        acc = fmaf(a[k], W_ba[k * 32 + n], acc);
    g_ba[(size_t)m * 32 + n] = acc;
}

// ---------------- causal depthwise conv (KS=4) + l2norm of q,k ----------------
__global__ void conv_act_kernel(const float* __restrict__ conv_w,
                                const float* __restrict__ conv_b)
{
    int bl  = blockIdx.x;
    int grp = blockIdx.y;
    int c   = grp * 128 + threadIdx.x;
    int l   = bl & (LL - 1);

    const float* base = g_qkvz + (size_t)bl * QKVZ_DIM + c;
    float w0 = conv_w[c*KSZ+0], w1 = conv_w[c*KSZ+1],
          w2 = conv_w[c*KSZ+2], w3 = conv_w[c*KSZ+3];
    float acc = conv_b[c];
    if (l >= 3) acc = fmaf(base[-3*QKVZ_DIM], w0, acc);
    if (l >= 2) acc = fmaf(base[-2*QKVZ_DIM], w1, acc);
    if (l >= 1) acc = fmaf(base[-1*QKVZ_DIM], w2, acc);
    acc = fmaf(base[0], w3, acc);

    if (grp < 32) {
        float ss = acc * acc;
        #pragma unroll
        for (int off = 16; off > 0; off >>= 1)
            ss += __shfl_xor_sync(0xffffffffu, ss, off);
        __shared__ float ws[4];
        if ((threadIdx.x & 31) == 0) ws[threadIdx.x >> 5] = ss;
        __syncthreads();
        float tot = ws[0] + ws[1] + ws[2] + ws[3];
        acc *= rsqrtf(tot + 1e-6f);
    }
    g_xqkv[(size_t)bl * CONV_DIM + c] = acc;
}

// ---------------- g / beta ----------------
__global__ void gate_kernel(const float* __restrict__ A_log,
                            const float* __restrict__ dt_bias)
{
    int i = blockIdx.x * blockDim.x + threadIdx.x;
    if (i >= BL * HH) return;
    int h = i & (HH - 1);
    int bl = i >> 4;
    float b_ = g_ba[(size_t)bl * 32 + h];
    float a_ = g_ba[(size_t)bl * 32 + 16 + h];
    float x  = a_ + dt_bias[h];
    float sp = (x > 20.f) ? x : log1pf(expf(x));
    g_g[i]    = -expf(A_log[h]) * sp;
    g_beta[i] = 1.f / (1.f + expf(-b_));
}

// ---------------- sequential delta-rule scan ----------------
__global__ __launch_bounds__(128)
void scan_kernel()
{
    const int bh   = blockIdx.x;
    const int half = blockIdx.y;
    const int b = bh >> 4, h = bh & 15;
    const int tid = threadIdx.x;
    const int col = tid & 63;
    const int rh  = tid >> 6;

    __shared__ float sk[128], sq[128], sv[64], red[128], red2[128];

    float S[64];
    #pragma unroll
    for (int r = 0; r < 64; r++) S[r] = 0.f;

    const float scale = 0.08838834764831845f;

    const size_t xbase = (size_t)b * LL * CONV_DIM + (size_t)h * 128;
    const size_t gbase = (size_t)b * LL * HH + h;

    const float* xp = g_xqkv + xbase;
    float qn = xp[tid];
    float kn = xp[2048 + tid];
    float vn = (tid < 64) ? xp[4096 + half*64 + tid] : 0.f;
    float gn = g_g[gbase];
    float bn = g_beta[gbase];

    for (int l = 0; l < LL; l++) {
        sq[tid] = qn; sk[tid] = kn;
        if (tid < 64) sv[tid] = vn;
        float gcur = gn, bcur = bn;
        __syncthreads();

        if (l + 1 < LL) {
            const float* xn = g_xqkv + xbase + (size_t)(l + 1) * CONV_DIM;
            qn = xn[tid];
            kn = xn[2048 + tid];
            if (tid < 64) vn = xn[4096 + half*64 + tid];
            gn = g_g[gbase + (size_t)(l + 1) * HH];
            bn = g_beta[gbase + (size_t)(l + 1) * HH];
        }

        float decay = expf(gcur);
        const float* skh = sk + rh * 64;
        float p0 = 0.f, p1 = 0.f, p2 = 0.f, p3 = 0.f;
        #pragma unroll
        for (int r = 0; r < 64; r += 4) {
            S[r+0] *= decay; p0 = fmaf(skh[r+0], S[r+0], p0);
            S[r+1] *= decay; p1 = fmaf(skh[r+1], S[r+1], p1);
            S[r+2] *= decay; p2 = fmaf(skh[r+2], S[r+2], p2);
            S[r+3] *= decay; p3 = fmaf(skh[r+3], S[r+3], p3);
        }
        red[tid] = (p0 + p1) + (p2 + p3);
        __syncthreads();

        float delta = (sv[col] - (red[col] + red[col + 64])) * bcur;

        const float* sqh = sq + rh * 64;
        p0 = p1 = p2 = p3 = 0.f;
        #pragma unroll
        for (int r = 0; r < 64; r += 4) {
            S[r+0] = fmaf(skh[r+0], delta, S[r+0]); p0 = fmaf(sqh[r+0], S[r+0], p0);
            S[r+1] = fmaf(skh[r+1], delta, S[r+1]); p1 = fmaf(sqh[r+1], S[r+1], p1);
            S[r+2] = fmaf(skh[r+2], delta, S[r+2]); p2 = fmaf(sqh[r+2], S[r+2], p2);
            S[r+3] = fmaf(skh[r+3], delta, S[r+3]); p3 = fmaf(sqh[r+3], S[r+3], p3);
        }
        red2[tid] = (p0 + p1) + (p2 + p3);
        __syncthreads();

        if (rh == 0) {
            size_t oi = ((size_t)(b * LL + l)) * VAL_DIM + h * 128 + half * 64 + col;
            g_o[oi] = (red2[col] + red2[col + 64]) * scale;
        }
    }
}

// ---------------- RMS norm + z gating + bf16 split (fused) ----------------
__global__ void norm_gate_kernel(const float* __restrict__ norm_w)
{
    int blh = blockIdx.x;
    int d   = threadIdx.x;
    size_t oi = (size_t)blh * DV + d;
    float o = g_o[oi];
    float ss = o * o;
    #pragma unroll
    for (int off = 16; off > 0; off >>= 1)
        ss += __shfl_xor_sync(0xffffffffu, ss, off);
    __shared__ float ws[4];
    if ((d & 31) == 0) ws[d >> 5] = ss;
    __syncthreads();
    float tot = ws[0] + ws[1] + ws[2] + ws[3];

    int bl = blh >> 4, h = blh & 15;
    float z = g_qkvz[(size_t)bl * QKVZ_DIM + CONV_DIM + h * DV + d];
    float sig = 1.f / (1.f + expf(-z));
    float r = o * rsqrtf(tot * (1.f / DV) + 1e-6f) * norm_w[d] * sig;
    __nv_bfloat16 hi, lo; split2(r, hi, lo);
    g_o_h[oi] = hi;
    g_o_l[oi] = lo;
}

// ---------------- launch ----------------
extern "C" void kernel_launch(void* const* d_in, const int* in_sizes, int n_in,
                              void* d_out, int out_size)
{
    const float* hidden  = (const float*)d_in[0];
    const float* W_qkvz  = (const float*)d_in[1];
    const float* W_ba    = (const float*)d_in[2];
    const float* conv_w  = (const float*)d_in[3];
    const float* conv_b  = (const float*)d_in[4];
    const float* A_log   = (const float*)d_in[5];
    const float* dt_bias = (const float*)d_in[6];
    const float* norm_w  = (const float*)d_in[7];
    const float* W_out   = (const float*)d_in[8];
    float* out = (float*)d_out;

    float *qkvz_p = nullptr;
    __nv_bfloat16 *hidh=nullptr,*hidl=nullptr,*wqh=nullptr,*wql=nullptr,
                  *woh=nullptr,*wol=nullptr,*oh=nullptr,*ol=nullptr;
    cudaGetSymbolAddress((void**)&qkvz_p, g_qkvz);
    cudaGetSymbolAddress((void**)&hidh, g_hid_h);
    cudaGetSymbolAddress((void**)&hidl, g_hid_l);
    cudaGetSymbolAddress((void**)&wqh,  g_Wq_h);
    cudaGetSymbolAddress((void**)&wql,  g_Wq_l);
    cudaGetSymbolAddress((void**)&woh,  g_Wo_h);
    cudaGetSymbolAddress((void**)&wol,  g_Wo_l);
    cudaGetSymbolAddress((void**)&oh,   g_o_h);
    cudaGetSymbolAddress((void**)&ol,   g_o_l);

    // 1) splits for GEMM1
    {
        size_t n4 = (size_t)BL * HID / 4;
        split_kernel<<<(unsigned)((n4 + 255)/256), 256>>>(hidden, hidh, hidl, n4);
        split_transpose_kernel<<<dim3(QKVZ_DIM/32, HID/32), dim3(32,8)>>>(W_qkvz, wqh, wql, HID, QKVZ_DIM);
    }

    // 2) GEMM1: qkvz = hidden @ W_qkvz   [4096 x 8192]
    gemm_bf16x3<<<dim3(QKVZ_DIM/128, BL/128), 256>>>(
        hidh, hidl, wqh, wql, qkvz_p, BL, QKVZ_DIM, HID);

    // 3) ba projection
    ba_gemm_kernel<<<BL/8, dim3(32, 8)>>>(hidden, W_ba);

    // 4) conv + l2norm
    conv_act_kernel<<<dim3(BL, CONV_DIM/128), 128>>>(conv_w, conv_b);

    // 5) g / beta
    gate_kernel<<<(BL*HH + 255)/256, 256>>>(A_log, dt_bias);

    // 6) scan
    scan_kernel<<<dim3(BB*HH, 2), 128>>>();

    // 7) norm + z gate + split for GEMM2 (fused)
    norm_gate_kernel<<<BL*HH, 128>>>(norm_w);

    // 8) split W_out
    split_transpose_kernel<<<dim3(VAL_DIM/32, HID/32), dim3(32,8)>>>(W_out, woh, wol, HID, VAL_DIM);

    // 9) GEMM2: out = o @ W_out  [4096 x 2048]
    gemm_bf16x3<<<dim3(VAL_DIM/128, BL/128), 256>>>(
        oh, ol, woh, wol, out, BL, VAL_DIM, HID);
}

// round 8
// speedup vs baseline: 2.0114x; 1.0714x over previous
#include <cuda_runtime.h>
#include <cuda_bf16.h>
#include <math.h>

// Problem constants
#define BB   4
#define LL   1024
#define HID  2048
#define HH   16
#define DK   128
#define DV   128
#define KSZ  4
#define KEY_DIM  (HH*DK)             // 2048
#define VAL_DIM  (HH*DV)             // 2048
#define CONV_DIM (2*KEY_DIM+VAL_DIM) // 6144
#define QKVZ_DIM (2*KEY_DIM+2*VAL_DIM) // 8192
#define BL   (BB*LL)                 // 4096

// ---------------- scratch (static device allocations) ----------------
__device__ float g_qkvz[(size_t)BL * QKVZ_DIM];
__device__ float g_ba  [(size_t)BL * 2 * HH];
__device__ float g_xqkv[(size_t)BL * CONV_DIM];
__device__ float g_g   [(size_t)BL * HH];
__device__ float g_beta[(size_t)BL * HH];
__device__ float g_o   [(size_t)BL * VAL_DIM];

__device__ __nv_bfloat16 g_hid_h[(size_t)BL * HID];
__device__ __nv_bfloat16 g_hid_l[(size_t)BL * HID];
__device__ __nv_bfloat16 g_Wq_h [(size_t)QKVZ_DIM * HID];  // transposed [N][K]
__device__ __nv_bfloat16 g_Wq_l [(size_t)QKVZ_DIM * HID];
__device__ __nv_bfloat16 g_Wo_h [(size_t)VAL_DIM * HID];   // transposed [N][K]
__device__ __nv_bfloat16 g_Wo_l [(size_t)VAL_DIM * HID];
__device__ __nv_bfloat16 g_o_h  [(size_t)BL * VAL_DIM];
__device__ __nv_bfloat16 g_o_l  [(size_t)BL * VAL_DIM];

// ---------------- helpers ----------------
__device__ __forceinline__ void split2(float x, __nv_bfloat16& h, __nv_bfloat16& l) {
    h = __float2bfloat16_rn(x);
    l = __float2bfloat16_rn(x - __bfloat162float(h));
}
__device__ __forceinline__ unsigned s2u(const void* p) {
    return (unsigned)__cvta_generic_to_shared(p);
}
#define CP16(daddr, gptr) \
    asm volatile("cp.async.cg.shared.global [%0], [%1], 16;\n" :: "r"(daddr), "l"(gptr))
#define CP_COMMIT() asm volatile("cp.async.commit_group;\n")
#define CP_WAIT(n)  asm volatile("cp.async.wait_group %0;\n" :: "n"(n))
#define LDSM4(r, addr) \
    asm volatile("ldmatrix.sync.aligned.m8n8.x4.shared.b16 {%0,%1,%2,%3}, [%4];\n" \
                 : "=r"((r)[0]), "=r"((r)[1]), "=r"((r)[2]), "=r"((r)[3]) : "r"(addr))
#define MMA_BF16(d, a, b0, b1) \
    asm volatile("mma.sync.aligned.m16n8k16.row.col.f32.bf16.bf16.f32 " \
                 "{%0,%1,%2,%3}, {%4,%5,%6,%7}, {%8,%9}, {%0,%1,%2,%3};\n" \
                 : "+f"((d)[0]), "+f"((d)[1]), "+f"((d)[2]), "+f"((d)[3]) \
                 : "r"((a)[0]), "r"((a)[1]), "r"((a)[2]), "r"((a)[3]), \
                   "r"(b0), "r"(b1))

// ---------------- split (elementwise) ----------------
__global__ void split_kernel(const float* __restrict__ X,
                             __nv_bfloat16* __restrict__ H,
                             __nv_bfloat16* __restrict__ L, size_t n4)
{
    size_t i = (size_t)blockIdx.x * blockDim.x + threadIdx.x;
    if (i >= n4) return;
    float4 v = ((const float4*)X)[i];
    __nv_bfloat16 h0,h1,h2,h3,l0,l1,l2,l3;
    split2(v.x,h0,l0); split2(v.y,h1,l1); split2(v.z,h2,l2); split2(v.w,h3,l3);
    __nv_bfloat162* Hp = (__nv_bfloat162*)(H + i*4);
    __nv_bfloat162* Lp = (__nv_bfloat162*)(L + i*4);
    Hp[0] = __nv_bfloat162(h0,h1); Hp[1] = __nv_bfloat162(h2,h3);
    Lp[0] = __nv_bfloat162(l0,l1); Lp[1] = __nv_bfloat162(l2,l3);
}

// ---------------- split + transpose: W[K][N] -> T[N][K] (hi/lo) ----------------
__global__ void split_transpose_kernel(const float* __restrict__ W,
                                       __nv_bfloat16* __restrict__ Th,
                                       __nv_bfloat16* __restrict__ Tl,
                                       int K, int N)
{
    __shared__ float t[32][33];
    int k0 = blockIdx.y * 32, n0 = blockIdx.x * 32;
    int tx = threadIdx.x, ty = threadIdx.y;
    #pragma unroll
    for (int i = 0; i < 4; i++)
        t[ty + i*8][tx] = W[(size_t)(k0 + ty + i*8) * N + n0 + tx];
    __syncthreads();
    #pragma unroll
    for (int i = 0; i < 4; i++) {
        int n = ty + i*8;
        float x = t[tx][n];
        __nv_bfloat16 h, l; split2(x, h, l);
        size_t o = (size_t)(n0 + n) * K + k0 + tx;
        Th[o] = h; Tl[o] = l;
    }
}

// ---------------- bf16x3 tensor-core GEMM (static 32KB smem, BK=16) ----------------
// C[M,N] = A[M,K] @ B[K,N]; A hi/lo [M][K]; B TRANSPOSED hi/lo [N][K].
// Block tile 128x128, 256 threads (warps 2x4, each 64x32), double-buffered BK=16.
// Smem tile: 128 rows x 32 bytes, XOR-swizzled: byte = row*32 + (kb ^ (((row>>2)&1)<<4)).
// MMAs issued term-major (hh x16, hl x16, lh x16) so same-accumulator reuses are
// >=16 issues apart -> no HMMA scoreboard stalls. One __syncthreads per k-iter.
#define TILE_B   4096                 // bytes per tile (128*32)
#define STAGE_B  (4*TILE_B)           // Ah, Al, Bh, Bl

__global__ __launch_bounds__(256)
void gemm_bf16x3(const __nv_bfloat16* __restrict__ Ah, const __nv_bfloat16* __restrict__ Al,
                 const __nv_bfloat16* __restrict__ Bh, const __nv_bfloat16* __restrict__ Bl,
                 float* __restrict__ C, int M, int N, int K)
{
    __shared__ __align__(16) unsigned char smbuf[2 * STAGE_B];   // 32 KB static

    const int tid = threadIdx.x, lane = tid & 31, warp = tid >> 5;
    const int wr = warp >> 2, wc = warp & 3;
    const int bm = blockIdx.y * 128, bn = blockIdx.x * 128;

    const char* gA_h = (const char*)(Ah + (size_t)bm * K);
    const char* gA_l = (const char*)(Al + (size_t)bm * K);
    const char* gB_h = (const char*)(Bh + (size_t)bn * K);
    const char* gB_l = (const char*)(Bl + (size_t)bn * K);

    float acc[4][4][4];
    #pragma unroll
    for (int i = 0; i < 4; i++)
        #pragma unroll
        for (int j = 0; j < 4; j++)
            #pragma unroll
            for (int r = 0; r < 4; r++) acc[i][j][r] = 0.f;

    // producer coords: 256 threads x 1 chunk(16B) per tile per stage
    const int prow   = tid >> 1;
    const int pkb    = (tid & 1) * 16;
    const int pdst   = prow * 32 + (pkb ^ (((prow >> 2) & 1) << 4));
    const size_t pgo = (size_t)prow * K * 2 + pkb;

    // consumer ldmatrix coords
    const int lrow = (lane & 7) + ((lane >> 3) & 1) * 8;
    const int lkb  = (lane >> 4) * 16;

    const int niter = K / 16;

    {
        unsigned char* base = smbuf;
        CP16(s2u(base + 0*TILE_B + pdst), gA_h + pgo);
        CP16(s2u(base + 1*TILE_B + pdst), gA_l + pgo);
        CP16(s2u(base + 2*TILE_B + pdst), gB_h + pgo);
        CP16(s2u(base + 3*TILE_B + pdst), gB_l + pgo);
    }
    CP_COMMIT();

    for (int it = 0; it < niter; it++) {
        const int s = it & 1;
        CP_WAIT(0);
        __syncthreads();     // stage s arrived; everyone done reading s^1 last iter

        if (it + 1 < niter) {        // prefetch into s^1, overlaps with MMAs below
            unsigned char* nb = smbuf + (s ^ 1) * STAGE_B;
            size_t go = pgo + (size_t)(it + 1) * 32;
            CP16(s2u(nb + 0*TILE_B + pdst), gA_h + go);
            CP16(s2u(nb + 1*TILE_B + pdst), gA_l + go);
            CP16(s2u(nb + 2*TILE_B + pdst), gB_h + go);
            CP16(s2u(nb + 3*TILE_B + pdst), gB_l + go);
            CP_COMMIT();
        }

        unsigned char* base = smbuf + s * STAGE_B;
        unsigned char* sAh = base + 0*TILE_B;
        unsigned char* sAl = base + 1*TILE_B;
        unsigned char* sBh = base + 2*TILE_B;
        unsigned char* sBl = base + 3*TILE_B;

        unsigned afh[4][4], afl[4][4], bfh[2][4], bfl[2][4];
        #pragma unroll
        for (int mt = 0; mt < 4; mt++) {
            int r = wr*64 + mt*16 + lrow;
            int off = r * 32 + (lkb ^ (((r >> 2) & 1) << 4));
            LDSM4(afh[mt], s2u(sAh + off));
            LDSM4(afl[mt], s2u(sAl + off));
        }
        #pragma unroll
        for (int p = 0; p < 2; p++) {
            int r = wc*32 + p*16 + lrow;
            int off = r * 32 + (lkb ^ (((r >> 2) & 1) << 4));
            LDSM4(bfh[p], s2u(sBh + off));
            LDSM4(bfl[p], s2u(sBl + off));
        }
        // term-major: 16 independent MMAs per run
        #pragma unroll
        for (int mt = 0; mt < 4; mt++)
            #pragma unroll
            for (int nt = 0; nt < 4; nt++) {
                int p = nt >> 1, q = nt & 1;
                MMA_BF16(acc[mt][nt], afh[mt], bfh[p][q], bfh[p][2+q]);
            }
        #pragma unroll
        for (int mt = 0; mt < 4; mt++)
            #pragma unroll
            for (int nt = 0; nt < 4; nt++) {
                int p = nt >> 1, q = nt & 1;
                MMA_BF16(acc[mt][nt], afh[mt], bfl[p][q], bfl[p][2+q]);
            }
        #pragma unroll
        for (int mt = 0; mt < 4; mt++)
            #pragma unroll
            for (int nt = 0; nt < 4; nt++) {
                int p = nt >> 1, q = nt & 1;
                MMA_BF16(acc[mt][nt], afl[mt], bfh[p][q], bfh[p][2+q]);
            }
    }

    const int g = lane >> 2, t4 = lane & 3;
    #pragma unroll
    for (int mt = 0; mt < 4; mt++) {
        #pragma unroll
        for (int nt = 0; nt < 4; nt++) {
            int row = bm + wr*64 + mt*16 + g;
            int col = bn + wc*32 + nt*8 + 2*t4;
            float2* p0 = (float2*)&C[(size_t)row * N + col];
            float2* p1 = (float2*)&C[(size_t)(row + 8) * N + col];
            *p0 = make_float2(acc[mt][nt][0], acc[mt][nt][1]);
            *p1 = make_float2(acc[mt][nt][2], acc[mt][nt][3]);
        }
    }
}

// ---------------- small GEMM for ba: [BL,2048] @ [2048,32] ----------------
// float4 A loads + 4 independent accumulator chains for MLP.
__global__ void ba_gemm_kernel(const float* __restrict__ hidden,
                               const float* __restrict__ W_ba)
{
    int m = blockIdx.x * blockDim.y + threadIdx.y;
    int n = threadIdx.x;
    const float4* a4 = (const float4*)(hidden + (size_t)m * HID);
    float acc0 = 0.f, acc1 = 0.f, acc2 = 0.f, acc3 = 0.f;
    #pragma unroll 4
    for (int k4 = 0; k4 < HID/4; k4++) {
        float4 av = a4[k4];
        const float* wb = W_ba + (size_t)k4 * 4 * 32 + n;
        acc0 = fmaf(av.x, wb[0],   acc0);
        acc1 = fmaf(av.y, wb[32],  acc1);
        acc2 = fmaf(av.z, wb[64],  acc2);
        acc3 = fmaf(av.w, wb[96],  acc3);
    }
    g_ba[(size_t)m * 32 + n] = (acc0 + acc1) + (acc2 + acc3);
}

// ---------------- causal depthwise conv (KS=4) + l2norm of q,k ----------------
__global__ void conv_act_kernel(const float* __restrict__ conv_w,
                                const float* __restrict__ conv_b)
{
    int bl  = blockIdx.x;
    int grp = blockIdx.y;
    int c   = grp * 128 + threadIdx.x;
    int l   = bl & (LL - 1);

    const float* base = g_qkvz + (size_t)bl * QKVZ_DIM + c;
    float w0 = conv_w[c*KSZ+0], w1 = conv_w[c*KSZ+1],
          w2 = conv_w[c*KSZ+2], w3 = conv_w[c*KSZ+3];
    float acc = conv_b[c];
    if (l >= 3) acc = fmaf(base[-3*QKVZ_DIM], w0, acc);
    if (l >= 2) acc = fmaf(base[-2*QKVZ_DIM], w1, acc);
    if (l >= 1) acc = fmaf(base[-1*QKVZ_DIM], w2, acc);
    acc = fmaf(base[0], w3, acc);

    if (grp < 32) {
        float ss = acc * acc;
        #pragma unroll
        for (int off = 16; off > 0; off >>= 1)
            ss += __shfl_xor_sync(0xffffffffu, ss, off);
        __shared__ float ws[4];
        if ((threadIdx.x & 31) == 0) ws[threadIdx.x >> 5] = ss;
        __syncthreads();
        float tot = ws[0] + ws[1] + ws[2] + ws[3];
        acc *= rsqrtf(tot + 1e-6f);
    }
    g_xqkv[(size_t)bl * CONV_DIM + c] = acc;
}

// ---------------- g / beta ----------------
__global__ void gate_kernel(const float* __restrict__ A_log,
                            const float* __restrict__ dt_bias)
{
    int i = blockIdx.x * blockDim.x + threadIdx.x;
    if (i >= BL * HH) return;
    int h = i & (HH - 1);
    int bl = i >> 4;
    float b_ = g_ba[(size_t)bl * 32 + h];
    float a_ = g_ba[(size_t)bl * 32 + 16 + h];
    float x  = a_ + dt_bias[h];
    float sp = (x > 20.f) ? x : log1pf(expf(x));
    g_g[i]    = -expf(A_log[h]) * sp;
    g_beta[i] = 1.f / (1.f + expf(-b_));
}

// ---------------- sequential delta-rule scan ----------------
// grid: (B*H, 2 dv-halves) = 128 blocks; block 256 threads.
// thread owns rows [rg*32, rg*32+32) of state column (half*64 + col), in registers.
__global__ __launch_bounds__(256)
void scan_kernel()
{
    const int bh   = blockIdx.x;
    const int half = blockIdx.y;
    const int b = bh >> 4, h = bh & 15;
    const int tid = threadIdx.x;
    const int col = tid & 63;     // 0..63
    const int rg  = tid >> 6;     // 0..3

    __shared__ float sk[128], sq[128], sv[64], red[256], red2[256];

    float S[32];
    #pragma unroll
    for (int r = 0; r < 32; r++) S[r] = 0.f;

    const float scale = 0.08838834764831845f;

    const size_t xbase = (size_t)b * LL * CONV_DIM + (size_t)h * 128;
    const size_t gbase = (size_t)b * LL * HH + h;

    // prefetch l = 0
    const float* xp = g_xqkv + xbase;
    float qn = 0.f, kn = 0.f, vn = 0.f;
    if (tid < 128) { qn = xp[tid]; kn = xp[2048 + tid]; }
    if (tid < 64)  vn = xp[4096 + half*64 + tid];
    float gn = g_g[gbase];
    float bn = g_beta[gbase];

    for (int l = 0; l < LL; l++) {
        if (tid < 128) { sq[tid] = qn; sk[tid] = kn; }
        if (tid < 64)  sv[tid] = vn;
        float gcur = gn, bcur = bn;
        __syncthreads();                                // (1) tiles visible

        if (l + 1 < LL) {
            const float* xn = g_xqkv + xbase + (size_t)(l + 1) * CONV_DIM;
            if (tid < 128) { qn = xn[tid]; kn = xn[2048 + tid]; }
            if (tid < 64)  vn = xn[4096 + half*64 + tid];
            gn = g_g[gbase + (size_t)(l + 1) * HH];
            bn = g_beta[gbase + (size_t)(l + 1) * HH];
        }

        float decay = expf(gcur);
        const float* skh = sk + rg * 32;
        float p0 = 0.f, p1 = 0.f, p2 = 0.f, p3 = 0.f;
        #pragma unroll
        for (int r = 0; r < 32; r += 4) {
            S[r+0] *= decay; p0 = fmaf(skh[r+0], S[r+0], p0);
            S[r+1] *= decay; p1 = fmaf(skh[r+1], S[r+1], p1);
            S[r+2] *= decay; p2 = fmaf(skh[r+2], S[r+2], p2);
            S[r+3] *= decay; p3 = fmaf(skh[r+3], S[r+3], p3);
        }
        red[tid] = (p0 + p1) + (p2 + p3);
        __syncthreads();                                // (2) partials visible

        float delta = (sv[col] -
            ((red[col] + red[col + 64]) + (red[col + 128] + red[col + 192]))) * bcur;

        const float* sqh = sq + rg * 32;
        p0 = p1 = p2 = p3 = 0.f;
        #pragma unroll
        for (int r = 0; r < 32; r += 4) {
            S[r+0] = fmaf(skh[r+0], delta, S[r+0]); p0 = fmaf(sqh[r+0], S[r+0], p0);
            S[r+1] = fmaf(skh[r+1], delta, S[r+1]); p1 = fmaf(sqh[r+1], S[r+1], p1);
            S[r+2] = fmaf(skh[r+2], delta, S[r+2]); p2 = fmaf(sqh[r+2], S[r+2], p2);
            S[r+3] = fmaf(skh[r+3], delta, S[r+3]); p3 = fmaf(sqh[r+3], S[r+3], p3);
        }
        red2[tid] = (p0 + p1) + (p2 + p3);
        __syncthreads();                                // (3) o partials visible

        if (rg == 0) {
            size_t oi = ((size_t)(b * LL + l)) * VAL_DIM + h * 128 + half * 64 + col;
            g_o[oi] = ((red2[col] + red2[col + 64]) +
                       (red2[col + 128] + red2[col + 192])) * scale;
        }
    }
}

// ---------------- RMS norm + z gating + bf16 split (fused) ----------------
__global__ void norm_gate_kernel(const float* __restrict__ norm_w)
{
    int blh = blockIdx.x;
    int d   = threadIdx.x;
    size_t oi = (size_t)blh * DV + d;
    float o = g_o[oi];
    float ss = o * o;
    #pragma unroll
    for (int off = 16; off > 0; off >>= 1)
        ss += __shfl_xor_sync(0xffffffffu, ss, off);
    __shared__ float ws[4];
    if ((d & 31) == 0) ws[d >> 5] = ss;
    __syncthreads();
    float tot = ws[0] + ws[1] + ws[2] + ws[3];

    int bl = blh >> 4, h = blh & 15;
    float z = g_qkvz[(size_t)bl * QKVZ_DIM + CONV_DIM + h * DV + d];
    float sig = 1.f / (1.f + expf(-z));
    float r = o * rsqrtf(tot * (1.f / DV) + 1e-6f) * norm_w[d] * sig;
    __nv_bfloat16 hi, lo; split2(r, hi, lo);
    g_o_h[oi] = hi;
    g_o_l[oi] = lo;
}

// ---------------- launch ----------------
extern "C" void kernel_launch(void* const* d_in, const int* in_sizes, int n_in,
                              void* d_out, int out_size)
{
    const float* hidden  = (const float*)d_in[0];
    const float* W_qkvz  = (const float*)d_in[1];
    const float* W_ba    = (const float*)d_in[2];
    const float* conv_w  = (const float*)d_in[3];
    const float* conv_b  = (const float*)d_in[4];
    const float* A_log   = (const float*)d_in[5];
    const float* dt_bias = (const float*)d_in[6];
    const float* norm_w  = (const float*)d_in[7];
    const float* W_out   = (const float*)d_in[8];
    float* out = (float*)d_out;

    float *qkvz_p = nullptr;
    __nv_bfloat16 *hidh=nullptr,*hidl=nullptr,*wqh=nullptr,*wql=nullptr,
                  *woh=nullptr,*wol=nullptr,*oh=nullptr,*ol=nullptr;
    cudaGetSymbolAddress((void**)&qkvz_p, g_qkvz);
    cudaGetSymbolAddress((void**)&hidh, g_hid_h);
    cudaGetSymbolAddress((void**)&hidl, g_hid_l);
    cudaGetSymbolAddress((void**)&wqh,  g_Wq_h);
    cudaGetSymbolAddress((void**)&wql,  g_Wq_l);
    cudaGetSymbolAddress((void**)&woh,  g_Wo_h);
    cudaGetSymbolAddress((void**)&wol,  g_Wo_l);
    cudaGetSymbolAddress((void**)&oh,   g_o_h);
    cudaGetSymbolAddress((void**)&ol,   g_o_l);

    // 1) splits for GEMM1
    {
        size_t n4 = (size_t)BL * HID / 4;
        split_kernel<<<(unsigned)((n4 + 255)/256), 256>>>(hidden, hidh, hidl, n4);
        split_transpose_kernel<<<dim3(QKVZ_DIM/32, HID/32), dim3(32,8)>>>(W_qkvz, wqh, wql, HID, QKVZ_DIM);
    }

    // 2) GEMM1: qkvz = hidden @ W_qkvz   [4096 x 8192]
    gemm_bf16x3<<<dim3(QKVZ_DIM/128, BL/128), 256>>>(
        hidh, hidl, wqh, wql, qkvz_p, BL, QKVZ_DIM, HID);

    // 3) ba projection
    ba_gemm_kernel<<<BL/8, dim3(32, 8)>>>(hidden, W_ba);

    // 4) conv + l2norm
    conv_act_kernel<<<dim3(BL, CONV_DIM/128), 128>>>(conv_w, conv_b);

    // 5) g / beta
    gate_kernel<<<(BL*HH + 255)/256, 256>>>(A_log, dt_bias);

    // 6) scan
    scan_kernel<<<dim3(BB*HH, 2), 256>>>();

    // 7) norm + z gate + split for GEMM2 (fused)
    norm_gate_kernel<<<BL*HH, 128>>>(norm_w);

    // 8) split W_out
    split_transpose_kernel<<<dim3(VAL_DIM/32, HID/32), dim3(32,8)>>>(W_out, woh, wol, HID, VAL_DIM);

    // 9) GEMM2: out = o @ W_out  [4096 x 2048]
    gemm_bf16x3<<<dim3(VAL_DIM/128, BL/128), 256>>>(
        oh, ol, woh, wol, out, BL, VAL_DIM, HID);
}